// round 1
// baseline (speedup 1.0000x reference)
#include <cuda_runtime.h>

// Problem constants
#define B_  32
#define N_  325
#define K_  20
#define SIN 12
#define S_  12      // S_OUT
#define C_  10
#define H_  48      // 4*S_OUT
#define BN  (B_ * N_)   // 10400
#define K1_BLOCKS ((BN + 255) / 256)   // 41

// Scratch (device globals: no allocation allowed)
__device__ float g_wh[BN * S_];
__device__ float g_hx[BN * H_];
__device__ float g_hy[BN * H_];
__device__ float g_whp[K1_BLOCKS];
__device__ float g_clp[BN];
__device__ float g_dsp[BN];

__device__ __forceinline__ float lrelu(float x) { return x >= 0.0f ? x : 0.5f * x; }

// ---------------------------------------------------------------------------
// Kernel 1: wh = leaky(x @ w_W + w_b);  hx = wh @ a1_W[:12];  hy = wh @ a1_W[12:]
// One thread per (b,n) row. Also per-block partial sum of wh (for wh.mean()).
// ---------------------------------------------------------------------------
__global__ void __launch_bounds__(256)
k_embed(const float* __restrict__ in, const float* __restrict__ wW,
        const float* __restrict__ wb, const float* __restrict__ a1W) {
    __shared__ float s_wW[SIN * S_];
    __shared__ float s_wb[S_];
    __shared__ float s_a1W[2 * S_ * H_];
    __shared__ float red[256];

    int t = threadIdx.x;
    for (int i = t; i < SIN * S_; i += 256) s_wW[i] = wW[i];
    if (t < S_) s_wb[t] = wb[t];
    for (int i = t; i < 2 * S_ * H_; i += 256) s_a1W[i] = a1W[i];
    __syncthreads();

    int row = blockIdx.x * 256 + t;
    float whsum = 0.0f;
    if (row < BN) {
        float x[SIN];
        #pragma unroll
        for (int i = 0; i < SIN; i++) x[i] = in[row * SIN + i];

        float wh[S_];
        #pragma unroll
        for (int j = 0; j < S_; j++) {
            float a = s_wb[j];
            #pragma unroll
            for (int i = 0; i < SIN; i++) a += x[i] * s_wW[i * S_ + j];
            wh[j] = lrelu(a);
            whsum += wh[j];
            g_wh[row * S_ + j] = wh[j];
        }
        #pragma unroll
        for (int j = 0; j < H_; j++) {
            float ax = 0.0f, ay = 0.0f;
            #pragma unroll
            for (int i = 0; i < S_; i++) {
                ax += wh[i] * s_a1W[i * H_ + j];
                ay += wh[i] * s_a1W[(S_ + i) * H_ + j];
            }
            g_hx[row * H_ + j] = ax;
            g_hy[row * H_ + j] = ay;
        }
    }
    red[t] = whsum;
    __syncthreads();
    for (int s = 128; s > 0; s >>= 1) {
        if (t < s) red[t] += red[t + s];
        __syncthreads();
    }
    if (t == 0) g_whp[blockIdx.x] = red[0];
}

// ---------------------------------------------------------------------------
// Kernel 2: one block per (b,n). Attention at K gathered neighbors, softmax,
// output einsum, normalized-wh dist matrix, cluster loss partials.
// ---------------------------------------------------------------------------
__global__ void __launch_bounds__(256)
k_main(const int* __restrict__ idxp, const float* __restrict__ a1b,
       const float* __restrict__ a2W, const float* __restrict__ a2b,
       float* __restrict__ out) {
    __shared__ float s_hx[H_];
    __shared__ float s_hy[K_ * H_];
    __shared__ float s_hid[K_ * H_];
    __shared__ float s_wht[K_ * S_];
    __shared__ float s_att[K_ * C_];
    __shared__ float s_wtn[K_ * S_];
    __shared__ float s_a2W[H_ * C_];
    __shared__ float s_a2b[C_];
    __shared__ float s_a1b[H_];
    __shared__ int   s_idx[K_];
    __shared__ float redA[256];
    __shared__ float redB[256];

    int bn = blockIdx.x;
    int b  = bn / N_;
    int t  = threadIdx.x;

    if (t < K_) s_idx[t] = idxp[bn * K_ + t];
    if (t < H_) { s_hx[t] = g_hx[bn * H_ + t]; s_a1b[t] = a1b[t]; }
    if (t < C_) s_a2b[t] = a2b[t];
    for (int i = t; i < H_ * C_; i += 256) s_a2W[i] = a2W[i];
    __syncthreads();

    // gather hy and wh for the K neighbors
    for (int i = t; i < K_ * H_; i += 256) {
        int k = i / H_, h = i % H_;
        s_hy[i] = g_hy[(b * N_ + s_idx[k]) * H_ + h];
    }
    for (int i = t; i < K_ * S_; i += 256) {
        int k = i / S_, s = i % S_;
        s_wht[i] = g_wh[(b * N_ + s_idx[k]) * S_ + s];
    }
    __syncthreads();

    // hidden[k][h] = leaky(hx[h] + hy[k][h] + a1b[h])
    for (int i = t; i < K_ * H_; i += 256) {
        int h = i % H_;
        s_hid[i] = lrelu(s_hx[h] + s_hy[i] + s_a1b[h]);
    }
    __syncthreads();

    // attention[k][c] = leaky(hidden[k] . a2W[:,c] + a2b[c])
    for (int i = t; i < K_ * C_; i += 256) {
        int k = i / C_, c = i % C_;
        float acc = s_a2b[c];
        #pragma unroll
        for (int h = 0; h < H_; h++) acc += s_hid[k * H_ + h] * s_a2W[h * C_ + c];
        s_att[i] = lrelu(acc);
    }
    __syncthreads();

    // softmax over C per k (max-subtracted), in place
    if (t < K_) {
        float m = s_att[t * C_];
        #pragma unroll
        for (int c = 1; c < C_; c++) m = fmaxf(m, s_att[t * C_ + c]);
        float sum = 0.0f;
        float e[C_];
        #pragma unroll
        for (int c = 0; c < C_; c++) { e[c] = __expf(s_att[t * C_ + c] - m); sum += e[c]; }
        float inv = 1.0f / sum;
        #pragma unroll
        for (int c = 0; c < C_; c++) s_att[t * C_ + c] = e[c] * inv;
    }
    // wtn[k] = wht[k] / (||wht[k]|| + 1e-8)  (independent of softmax; same warp-range guard)
    __syncthreads();
    if (t < K_) {
        float nq = 0.0f;
        #pragma unroll
        for (int s = 0; s < S_; s++) { float v = s_wht[t * S_ + s]; nq += v * v; }
        float inv = 1.0f / (sqrtf(nq) + 1e-8f);
        #pragma unroll
        for (int s = 0; s < S_; s++) s_wtn[t * S_ + s] = s_wht[t * S_ + s] * inv;
    }
    __syncthreads();

    // output_data[b,n,c,s] = sum_k att[k][c] * wht[k][s]
    for (int i = t; i < C_ * S_; i += 256) {
        int c = i / S_, s = i % S_;
        float acc = 0.0f;
        #pragma unroll
        for (int k = 0; k < K_; k++) acc += s_att[k * C_ + c] * s_wht[k * S_ + s];
        out[(bn * C_ + c) * S_ + s] = acc;
    }

    // pairs (k,l): dist, cluster loss
    float cl = 0.0f, ds = 0.0f;
    for (int i = t; i < K_ * K_; i += 256) {
        int k = i / K_, l = i % K_;
        float d = 0.0f;
        #pragma unroll
        for (int s = 0; s < S_; s++) d += s_wtn[k * S_ + s] * s_wtn[l * S_ + s];
        ds += d;
        if (k != l) {
            float p = 0.0f;
            #pragma unroll
            for (int c = 0; c < C_; c++) p += s_att[k * C_ + c] * s_att[l * C_ + c];
            p = fminf(fmaxf(p, 1e-4f), 1.0f - 1e-4f);
            float lp = logf(p);
            float same = (d >= 0.5f) ? 1.0f : 0.0f;
            cl += (1.0f - 2.0f * same) * lp;   // -(same*lp - (1-same)*lp)
        }
    }
    redA[t] = cl;
    redB[t] = ds;
    __syncthreads();
    for (int s = 128; s > 0; s >>= 1) {
        if (t < s) { redA[t] += redA[t + s]; redB[t] += redB[t + s]; }
        __syncthreads();
    }
    if (t == 0) { g_clp[bn] = redA[0]; g_dsp[bn] = redB[0]; }
}

// ---------------------------------------------------------------------------
// Kernel 3: deterministic final reduction of scalars
// ---------------------------------------------------------------------------
__global__ void __launch_bounds__(256)
k_reduce(float* __restrict__ out, int scalar_base) {
    __shared__ double red[256];
    int t = threadIdx.x;
    double cl = 0.0, ds = 0.0, wh = 0.0;
    for (int i = t; i < BN; i += 256) { cl += (double)g_clp[i]; ds += (double)g_dsp[i]; }
    for (int i = t; i < K1_BLOCKS; i += 256) wh += (double)g_whp[i];

    red[t] = cl; __syncthreads();
    for (int s = 128; s > 0; s >>= 1) { if (t < s) red[t] += red[t + s]; __syncthreads(); }
    double clsum = red[0]; __syncthreads();

    red[t] = ds; __syncthreads();
    for (int s = 128; s > 0; s >>= 1) { if (t < s) red[t] += red[t + s]; __syncthreads(); }
    double dsum = red[0]; __syncthreads();

    red[t] = wh; __syncthreads();
    for (int s = 128; s > 0; s >>= 1) { if (t < s) red[t] += red[t + s]; __syncthreads(); }
    double whsum = red[0];

    if (t == 0) {
        out[scalar_base + 0] = (float)(clsum / (double)BN);
        out[scalar_base + 1] = (float)(dsum / ((double)BN * K_ * K_));
        out[scalar_base + 2] = (float)(whsum / ((double)BN * S_));
    }
}

// ---------------------------------------------------------------------------
// Launch. Input order (metadata): fushed_features (unused), input_data, w_W,
// w_b, a1_W, a1_b, a2_W, a2_b, adj_mx_topk_index.
// ---------------------------------------------------------------------------
extern "C" void kernel_launch(void* const* d_in, const int* in_sizes, int n_in,
                              void* d_out, int out_size) {
    const float* input_data = (const float*)d_in[1];
    const float* wW  = (const float*)d_in[2];
    const float* wb  = (const float*)d_in[3];
    const float* a1W = (const float*)d_in[4];
    const float* a1b = (const float*)d_in[5];
    const float* a2W = (const float*)d_in[6];
    const float* a2b = (const float*)d_in[7];
    const int*   idx = (const int*)d_in[8];
    float* out = (float*)d_out;

    k_embed<<<K1_BLOCKS, 256>>>(input_data, wW, wb, a1W);
    k_main<<<BN, 256>>>(idx, a1b, a2W, a2b, out);
    k_reduce<<<1, 256>>>(out, out_size - 3);
}

// round 3
// speedup vs baseline: 1.0666x; 1.0666x over previous
#include <cuda_runtime.h>

// Problem constants
#define B_  32
#define N_  325
#define K_  20
#define SIN 12
#define S_  12      // S_OUT
#define C_  10
#define H_  48      // 4*S_OUT
#define SA  12      // padded attention row stride
#define BN  (B_ * N_)          // 10400
#define WPB 8                  // warps per block in k_main
#define K1_BLOCKS ((2 * BN + 255) / 256)   // 82

// Scratch (device globals: no allocation allowed)
__device__ float g_wh[BN * S_];
__device__ float g_hx[BN * H_];
__device__ float g_hy[BN * H_];
__device__ float g_whp[K1_BLOCKS];
__device__ float g_clp[BN];
__device__ float g_dsp[BN];

__device__ __forceinline__ float lrelu(float x) { return x >= 0.0f ? x : 0.5f * x; }

// ---------------------------------------------------------------------------
// Kernel 1: wh = leaky(x @ w_W + w_b);  hx = wh @ a1_W[:12];  hy = wh @ a1_W[12:]
// TWO threads per row: half 0 computes hx (and writes wh + whsum), half 1 hy.
// Weights transposed in smem for float4 dot products.
// ---------------------------------------------------------------------------
__global__ void __launch_bounds__(256)
k_embed(const float* __restrict__ in, const float* __restrict__ wW,
        const float* __restrict__ wb, const float* __restrict__ a1W) {
    __shared__ __align__(16) float s_wWt[S_ * SIN];        // [j][i]
    __shared__ __align__(16) float s_wb[S_];
    __shared__ __align__(16) float s_a1Wt[2 * H_ * S_];    // [half][j][i]
    __shared__ float s_red[8];

    int t = threadIdx.x;
    for (int d = t; d < S_ * SIN; d += 256) {
        int j = d / SIN, i = d % SIN;
        s_wWt[d] = wW[i * S_ + j];
    }
    if (t < S_) s_wb[t] = wb[t];
    for (int d = t; d < 2 * H_ * S_; d += 256) {
        int half = d / (H_ * S_);
        int r = d % (H_ * S_);
        int j = r / S_, i = r % S_;
        s_a1Wt[d] = a1W[(half * S_ + i) * H_ + j];
    }
    __syncthreads();

    int gid  = blockIdx.x * 256 + t;
    int row  = gid >> 1;
    int half = gid & 1;
    float whsum = 0.0f;

    if (row < BN) {
        // load input row (12 floats)
        float x[SIN];
        const float4* in4 = (const float4*)(in + row * SIN);
        #pragma unroll
        for (int q = 0; q < 3; q++) {
            float4 v = in4[q];
            x[q*4+0] = v.x; x[q*4+1] = v.y; x[q*4+2] = v.z; x[q*4+3] = v.w;
        }
        // wh
        float wh[S_];
        #pragma unroll
        for (int j = 0; j < S_; j++) {
            float a = s_wb[j];
            const float4* wr = (const float4*)(s_wWt + j * SIN);
            #pragma unroll
            for (int q = 0; q < 3; q++) {
                float4 v = wr[q];
                a += x[q*4+0]*v.x + x[q*4+1]*v.y + x[q*4+2]*v.z + x[q*4+3]*v.w;
            }
            wh[j] = lrelu(a);
        }
        if (half == 0) {
            float4* wo = (float4*)(g_wh + row * S_);
            #pragma unroll
            for (int q = 0; q < 3; q++)
                wo[q] = make_float4(wh[q*4+0], wh[q*4+1], wh[q*4+2], wh[q*4+3]);
            #pragma unroll
            for (int j = 0; j < S_; j++) whsum += wh[j];
        }
        // hx or hy
        const float* wt = s_a1Wt + half * H_ * S_;
        float* dst = (half == 0 ? g_hx : g_hy) + row * H_;
        #pragma unroll
        for (int j4 = 0; j4 < H_ / 4; j4++) {
            float o[4];
            #pragma unroll
            for (int jj = 0; jj < 4; jj++) {
                int j = j4 * 4 + jj;
                float a = 0.0f;
                const float4* wr = (const float4*)(wt + j * S_);
                #pragma unroll
                for (int q = 0; q < 3; q++) {
                    float4 v = wr[q];
                    a += wh[q*4+0]*v.x + wh[q*4+1]*v.y + wh[q*4+2]*v.z + wh[q*4+3]*v.w;
                }
                o[jj] = a;
            }
            ((float4*)dst)[j4] = make_float4(o[0], o[1], o[2], o[3]);
        }
    }
    // whsum reduction (only half==0 threads contribute)
    #pragma unroll
    for (int off = 16; off > 0; off >>= 1)
        whsum += __shfl_down_sync(0xffffffffu, whsum, off);
    if ((t & 31) == 0) s_red[t >> 5] = whsum;
    __syncthreads();
    if (t == 0) {
        float s = 0.0f;
        #pragma unroll
        for (int w = 0; w < 8; w++) s += s_red[w];
        g_whp[blockIdx.x] = s;
    }
}

// ---------------------------------------------------------------------------
// Kernel 2: ONE WARP per (b,n). 8 warps/block, no __syncthreads after prolog.
// ---------------------------------------------------------------------------
__global__ void __launch_bounds__(256)
k_main(const int* __restrict__ idxp, const float* __restrict__ a1b,
       const float* __restrict__ a2W, const float* __restrict__ a2b,
       float* __restrict__ out) {
    __shared__ __align__(16) float s_a2Wt[C_ * H_];        // [c][h]  1920B
    __shared__ __align__(16) float s_a1b[H_];
    __shared__ __align__(16) float s_a2b[12];
    __shared__ __align__(16) float s_hid[WPB][K_ * H_];    // 30720B (hy -> hidden)
    __shared__ __align__(16) float s_wht[WPB][K_ * S_];    // 7680B  (wht -> wtn)
    __shared__ __align__(16) float s_att[WPB][K_ * SA];    // 7680B  (padded rows)
    __shared__ int s_idx[WPB][K_];

    int t = threadIdx.x;
    int w = t >> 5;
    int lane = t & 31;
    int bn = blockIdx.x * WPB + w;
    int b  = bn / N_;

    // block-shared weights
    for (int d = t; d < C_ * H_; d += 256) {
        int c = d / H_, h = d % H_;
        s_a2Wt[d] = a2W[h * C_ + c];
    }
    if (t < H_) s_a1b[t] = a1b[t];
    if (t < C_) s_a2b[t] = a2b[t];
    __syncthreads();

    if (lane < K_) s_idx[w][lane] = idxp[bn * K_ + lane];
    __syncwarp();

    // gather hy and fuse hidden = lrelu(hx + hy + a1b)   (240 float4)
    {
        const float4* hx4 = (const float4*)(g_hx + bn * H_);
        const float4* b4  = (const float4*)s_a1b;
        float4* hid4 = (float4*)s_hid[w];
        for (int i4 = lane; i4 < K_ * (H_/4); i4 += 32) {
            int k = i4 / (H_/4), f = i4 % (H_/4);
            const float4* hy4 = (const float4*)(g_hy + (b * N_ + s_idx[w][k]) * H_);
            float4 hy = hy4[f], hx = hx4[f], bb = b4[f];
            float4 r;
            r.x = lrelu(hy.x + hx.x + bb.x);
            r.y = lrelu(hy.y + hx.y + bb.y);
            r.z = lrelu(hy.z + hx.z + bb.z);
            r.w = lrelu(hy.w + hx.w + bb.w);
            hid4[i4] = r;
        }
    }
    // gather wh_topk (60 float4)
    {
        float4* wt4 = (float4*)s_wht[w];
        for (int i4 = lane; i4 < K_ * (S_/4); i4 += 32) {
            int k = i4 / (S_/4), f = i4 % (S_/4);
            wt4[i4] = ((const float4*)(g_wh + (b * N_ + s_idx[w][k]) * S_))[f];
        }
    }
    __syncwarp();

    // attention[k][c] = lrelu(hid[k] . a2Wt[c] + a2b[c]),  padded rows (c=10,11 -> 0)
    for (int o = lane; o < K_ * SA; o += 32) {
        int k = o / SA, c = o % SA;
        float v = 0.0f;
        if (c < C_) {
            float acc = s_a2b[c];
            const float4* hr = (const float4*)(s_hid[w] + k * H_);
            const float4* ar = (const float4*)(s_a2Wt + c * H_);
            #pragma unroll
            for (int q = 0; q < H_/4; q++) {
                float4 hv = hr[q], av = ar[q];
                acc += hv.x*av.x + hv.y*av.y + hv.z*av.z + hv.w*av.w;
            }
            v = lrelu(acc);
        }
        s_att[w][o] = v;
    }
    __syncwarp();

    // softmax over C per k
    if (lane < K_) {
        float* a = s_att[w] + lane * SA;
        float m = a[0];
        #pragma unroll
        for (int c = 1; c < C_; c++) m = fmaxf(m, a[c]);
        float e[C_], sum = 0.0f;
        #pragma unroll
        for (int c = 0; c < C_; c++) { e[c] = __expf(a[c] - m); sum += e[c]; }
        float inv = 1.0f / sum;
        #pragma unroll
        for (int c = 0; c < C_; c++) a[c] = e[c] * inv;
    }
    __syncwarp();

    // output_data[b,n,c,s] = sum_k att[k][c] * wht[k][s]
    for (int o = lane; o < C_ * S_; o += 32) {
        int c = o / S_, s = o % S_;
        float acc = 0.0f;
        #pragma unroll
        for (int k = 0; k < K_; k++)
            acc += s_att[w][k * SA + c] * s_wht[w][k * S_ + s];
        out[bn * C_ * S_ + o] = acc;
    }
    __syncwarp();

    // normalize wht in place -> wtn
    if (lane < K_) {
        float* r = s_wht[w] + lane * S_;
        float nq = 0.0f;
        #pragma unroll
        for (int s = 0; s < S_; s++) nq += r[s] * r[s];
        float inv = 1.0f / (sqrtf(nq) + 1e-8f);
        #pragma unroll
        for (int s = 0; s < S_; s++) r[s] *= inv;
    }
    __syncwarp();

    // pairs (k,l): dist mean partial + cluster loss partial (float4 dots)
    float cl = 0.0f, ds = 0.0f;
    for (int i = lane; i < K_ * K_; i += 32) {
        int k = i / K_, l = i % K_;
        const float4* wk = (const float4*)(s_wht[w] + k * S_);
        const float4* wl = (const float4*)(s_wht[w] + l * S_);
        float d = 0.0f;
        #pragma unroll
        for (int q = 0; q < S_/4; q++) {
            float4 a = wk[q], c4 = wl[q];
            d += a.x*c4.x + a.y*c4.y + a.z*c4.z + a.w*c4.w;
        }
        ds += d;
        if (k != l) {
            const float4* ak = (const float4*)(s_att[w] + k * SA);
            const float4* al = (const float4*)(s_att[w] + l * SA);
            float p = 0.0f;
            #pragma unroll
            for (int q = 0; q < SA/4; q++) {
                float4 a = ak[q], c4 = al[q];
                p += a.x*c4.x + a.y*c4.y + a.z*c4.z + a.w*c4.w;
            }
            p = fminf(fmaxf(p, 1e-4f), 1.0f - 1e-4f);
            float lp = logf(p);
            float same = (d >= 0.5f) ? 1.0f : 0.0f;
            cl += (1.0f - 2.0f * same) * lp;
        }
    }
    #pragma unroll
    for (int off = 16; off > 0; off >>= 1) {
        cl += __shfl_down_sync(0xffffffffu, cl, off);
        ds += __shfl_down_sync(0xffffffffu, ds, off);
    }
    if (lane == 0) { g_clp[bn] = cl; g_dsp[bn] = ds; }
}

// ---------------------------------------------------------------------------
// Kernel 3: deterministic final reduction of scalars
// ---------------------------------------------------------------------------
__global__ void __launch_bounds__(256)
k_reduce(float* __restrict__ out, int scalar_base) {
    __shared__ double red[256];
    int t = threadIdx.x;
    double cl = 0.0, ds = 0.0, wh = 0.0;
    for (int i = t; i < BN; i += 256) { cl += (double)g_clp[i]; ds += (double)g_dsp[i]; }
    for (int i = t; i < K1_BLOCKS; i += 256) wh += (double)g_whp[i];

    red[t] = cl; __syncthreads();
    for (int s = 128; s > 0; s >>= 1) { if (t < s) red[t] += red[t + s]; __syncthreads(); }
    double clsum = red[0]; __syncthreads();

    red[t] = ds; __syncthreads();
    for (int s = 128; s > 0; s >>= 1) { if (t < s) red[t] += red[t + s]; __syncthreads(); }
    double dsum = red[0]; __syncthreads();

    red[t] = wh; __syncthreads();
    for (int s = 128; s > 0; s >>= 1) { if (t < s) red[t] += red[t + s]; __syncthreads(); }
    double whsum = red[0];

    if (t == 0) {
        out[scalar_base + 0] = (float)(clsum / (double)BN);
        out[scalar_base + 1] = (float)(dsum / ((double)BN * K_ * K_));
        out[scalar_base + 2] = (float)(whsum / ((double)BN * S_));
    }
}

// ---------------------------------------------------------------------------
// Launch. Input order: fushed_features (unused), input_data, w_W, w_b,
// a1_W, a1_b, a2_W, a2_b, adj_mx_topk_index.
// ---------------------------------------------------------------------------
extern "C" void kernel_launch(void* const* d_in, const int* in_sizes, int n_in,
                              void* d_out, int out_size) {
    const float* input_data = (const float*)d_in[1];
    const float* wW  = (const float*)d_in[2];
    const float* wb  = (const float*)d_in[3];
    const float* a1W = (const float*)d_in[4];
    const float* a1b = (const float*)d_in[5];
    const float* a2W = (const float*)d_in[6];
    const float* a2b = (const float*)d_in[7];
    const int*   idx = (const int*)d_in[8];
    float* out = (float*)d_out;

    k_embed<<<K1_BLOCKS, 256>>>(input_data, wW, wb, a1W);
    k_main<<<(BN + WPB - 1) / WPB, 256>>>(idx, a1b, a2W, a2b, out);
    k_reduce<<<1, 256>>>(out, out_size - 3);
}

// round 4
// speedup vs baseline: 1.1880x; 1.1138x over previous
#include <cuda_runtime.h>

// Problem constants
#define B_  32
#define N_  325
#define K_  20
#define SIN 12
#define S_  12      // S_OUT
#define C_  10
#define H_  48      // 4*S_OUT
#define SA  12      // padded attention row stride (floats)
#define AW  52      // padded a2Wt row stride (floats) — 52c mod 32 distinct -> conflict-free
#define BN  (B_ * N_)          // 10400
#define WPB 8                  // warps per block in k_main
#define K1T 4                  // threads per row in k_embed
#define K1_BLOCKS ((K1T * BN) / 128)   // 325

// Scratch (device globals: no allocation allowed)
__device__ float g_wh[BN * S_];
__device__ float g_hx[BN * H_];
__device__ float g_hy[BN * H_];
__device__ float g_whp[K1_BLOCKS];
__device__ float g_clp[BN];
__device__ float g_dsp[BN];

__device__ __forceinline__ float lrelu(float x) { return x >= 0.0f ? x : 0.5f * x; }

// packed f32x2 helpers (SASS FFMA2 — PTX-only path)
__device__ __forceinline__ void ffma2(unsigned long long& d, unsigned long long a, unsigned long long b) {
    asm("fma.rn.f32x2 %0, %1, %2, %0;" : "+l"(d) : "l"(a), "l"(b));
}
__device__ __forceinline__ unsigned long long pack2(float lo, float hi) {
    unsigned long long r; asm("mov.b64 %0, {%1, %2};" : "=l"(r) : "f"(lo), "f"(hi)); return r;
}
__device__ __forceinline__ float sum2(unsigned long long v) {
    float lo, hi; asm("mov.b64 {%0, %1}, %2;" : "=f"(lo), "=f"(hi) : "l"(v)); return lo + hi;
}

// ---------------------------------------------------------------------------
// Kernel 1: wh = leaky(x @ w_W + w_b);  [hx|hy] = wh @ a1_W
// FOUR threads per row: each recomputes wh (cheap) and produces 24 of the 96
// combined hx||hy outputs. 325 blocks of 128 -> all SMs covered.
// ---------------------------------------------------------------------------
__global__ void __launch_bounds__(128)
k_embed(const float* __restrict__ in, const float* __restrict__ wW,
        const float* __restrict__ wb, const float* __restrict__ a1W) {
    __shared__ __align__(16) float s_wWt[S_ * SIN];      // [j][i]
    __shared__ __align__(16) float s_wb[S_];
    __shared__ __align__(16) float s_a1Wt[2 * H_ * S_];  // [o][i], o in [0,96): half=o/48, j=o%48
    __shared__ float s_red[4];

    int t = threadIdx.x;
    for (int d = t; d < S_ * SIN; d += 128) {
        int j = d / SIN, i = d % SIN;
        s_wWt[d] = wW[i * S_ + j];
    }
    if (t < S_) s_wb[t] = wb[t];
    for (int d = t; d < 2 * H_ * S_; d += 128) {
        int o = d / S_, i = d % S_;
        int half = o / H_, j = o % H_;
        s_a1Wt[d] = a1W[(half * S_ + i) * H_ + j];
    }
    __syncthreads();

    int gid = blockIdx.x * 128 + t;
    int row = gid >> 2;
    int sub = gid & 3;
    float whsum = 0.0f;

    {
        float x[SIN];
        const float4* in4 = (const float4*)(in + row * SIN);
        #pragma unroll
        for (int q = 0; q < 3; q++) {
            float4 v = in4[q];
            x[q*4+0] = v.x; x[q*4+1] = v.y; x[q*4+2] = v.z; x[q*4+3] = v.w;
        }
        float wh[S_];
        #pragma unroll
        for (int j = 0; j < S_; j++) {
            float a = s_wb[j];
            const float4* wr = (const float4*)(s_wWt + j * SIN);
            #pragma unroll
            for (int q = 0; q < 3; q++) {
                float4 v = wr[q];
                a += x[q*4+0]*v.x + x[q*4+1]*v.y + x[q*4+2]*v.z + x[q*4+3]*v.w;
            }
            wh[j] = lrelu(a);
        }
        if (sub == 0) {
            float4* wo = (float4*)(g_wh + row * S_);
            #pragma unroll
            for (int q = 0; q < 3; q++)
                wo[q] = make_float4(wh[q*4+0], wh[q*4+1], wh[q*4+2], wh[q*4+3]);
            #pragma unroll
            for (int j = 0; j < S_; j++) whsum += wh[j];
        }
        // this thread's 24 outputs: combined index o0..o0+23
        int o0 = sub * 24;
        int half = o0 / H_;                 // 0 -> hx, 1 -> hy
        int j0 = o0 % H_;
        float* dst = (half == 0 ? g_hx : g_hy) + row * H_ + j0;
        const float* wt = s_a1Wt + o0 * S_;
        #pragma unroll
        for (int j4 = 0; j4 < 6; j4++) {
            float o[4];
            #pragma unroll
            for (int jj = 0; jj < 4; jj++) {
                float a = 0.0f;
                const float4* wr = (const float4*)(wt + (j4 * 4 + jj) * S_);
                #pragma unroll
                for (int q = 0; q < 3; q++) {
                    float4 v = wr[q];
                    a += wh[q*4+0]*v.x + wh[q*4+1]*v.y + wh[q*4+2]*v.z + wh[q*4+3]*v.w;
                }
                o[jj] = a;
            }
            ((float4*)dst)[j4] = make_float4(o[0], o[1], o[2], o[3]);
        }
    }
    // whsum reduction (only sub==0 contribute)
    #pragma unroll
    for (int off = 16; off > 0; off >>= 1)
        whsum += __shfl_down_sync(0xffffffffu, whsum, off);
    if ((t & 31) == 0) s_red[t >> 5] = whsum;
    __syncthreads();
    if (t == 0) g_whp[blockIdx.x] = s_red[0] + s_red[1] + s_red[2] + s_red[3];
}

// ---------------------------------------------------------------------------
// Kernel 2: ONE WARP per (b,n). Unrolled predicated loops for MLP,
// f32x2 packed FMA in all dot products, conflict-free smem strides.
// ---------------------------------------------------------------------------
__global__ void __launch_bounds__(256)
k_main(const int* __restrict__ idxp, const float* __restrict__ a1b,
       const float* __restrict__ a2W, const float* __restrict__ a2b,
       float* __restrict__ out) {
    __shared__ __align__(16) float s_a2Wt[C_ * AW];        // [c][h], padded stride 52
    __shared__ __align__(16) float s_a1b[H_];
    __shared__ __align__(16) float s_a2b[12];
    __shared__ __align__(16) float s_hid[WPB][K_ * H_];    // hidden
    __shared__ __align__(16) float s_wht[WPB][K_ * S_];    // wh_topk -> wtn
    __shared__ __align__(16) float s_att[WPB][K_ * SA];    // attention (padded rows)
    __shared__ int s_idx[WPB][K_];

    int t = threadIdx.x;
    int w = t >> 5;
    int lane = t & 31;
    int bn = blockIdx.x * WPB + w;
    int b  = bn / N_;

    for (int d = t; d < C_ * H_; d += 256) {
        int c = d / H_, h = d % H_;
        s_a2Wt[c * AW + h] = a2W[h * C_ + c];
    }
    if (t < H_) s_a1b[t] = a1b[t];
    if (t < C_) s_a2b[t] = a2b[t];
    __syncthreads();

    if (lane < K_) s_idx[w][lane] = idxp[bn * K_ + lane];
    __syncwarp();

    // gather hy + fuse hidden = lrelu(hx + hy + a1b)   (240 float4, unrolled, MLP 8)
    {
        const float4* hx4 = (const float4*)(g_hx + bn * H_);
        const float4* b4  = (const float4*)s_a1b;
        float4* hid4 = (float4*)s_hid[w];
        #pragma unroll
        for (int it = 0; it < 8; it++) {
            int i4 = lane + it * 32;
            if (it < 7 || i4 < K_ * (H_/4)) {
                int k = i4 / (H_/4), f = i4 % (H_/4);
                float4 hy = ((const float4*)(g_hy + (b * N_ + s_idx[w][k]) * H_))[f];
                float4 hx = hx4[f], bb = b4[f];
                float4 r;
                r.x = lrelu(hy.x + hx.x + bb.x);
                r.y = lrelu(hy.y + hx.y + bb.y);
                r.z = lrelu(hy.z + hx.z + bb.z);
                r.w = lrelu(hy.w + hx.w + bb.w);
                hid4[i4] = r;
            }
        }
    }
    // gather wh_topk (60 float4, unrolled)
    {
        float4* wt4 = (float4*)s_wht[w];
        #pragma unroll
        for (int it = 0; it < 2; it++) {
            int i4 = lane + it * 32;
            if (it < 1 || i4 < K_ * (S_/4)) {
                int k = i4 / (S_/4), f = i4 % (S_/4);
                wt4[i4] = ((const float4*)(g_wh + (b * N_ + s_idx[w][k]) * S_))[f];
            }
        }
    }
    __syncwarp();

    // attention[k][c] = lrelu(hid[k] . a2Wt[c] + a2b[c])  — f32x2 FMA
    #pragma unroll
    for (int it = 0; it < 7; it++) {
        int o = lane + it * 32;
        if (it < 6 || o < K_ * C_) {
            int k = o / C_, c = o % C_;
            const ulonglong2* hr = (const ulonglong2*)(s_hid[w] + k * H_);
            const ulonglong2* ar = (const ulonglong2*)(s_a2Wt + c * AW);
            unsigned long long acc2 = pack2(s_a2b[c], 0.0f);
            #pragma unroll
            for (int q = 0; q < H_/4; q++) {
                ulonglong2 hv = hr[q], av = ar[q];
                ffma2(acc2, hv.x, av.x);
                ffma2(acc2, hv.y, av.y);
            }
            s_att[w][k * SA + c] = lrelu(sum2(acc2));
        }
    }
    __syncwarp();

    // softmax over C per k; zero the two pad slots
    if (lane < K_) {
        float* a = s_att[w] + lane * SA;
        float m = a[0];
        #pragma unroll
        for (int c = 1; c < C_; c++) m = fmaxf(m, a[c]);
        float e[C_], sum = 0.0f;
        #pragma unroll
        for (int c = 0; c < C_; c++) { e[c] = __expf(a[c] - m); sum += e[c]; }
        float inv = 1.0f / sum;
        #pragma unroll
        for (int c = 0; c < C_; c++) a[c] = e[c] * inv;
        a[10] = 0.0f; a[11] = 0.0f;
    }
    __syncwarp();

    // output_data[b,n,c,s] = sum_k att[k][c] * wht[k][s]
    #pragma unroll
    for (int it = 0; it < 4; it++) {
        int o = lane + it * 32;
        if (it < 3 || o < C_ * S_) {
            int c = o / S_, s = o % S_;
            float acc = 0.0f;
            #pragma unroll
            for (int k = 0; k < K_; k++)
                acc += s_att[w][k * SA + c] * s_wht[w][k * S_ + s];
            out[bn * C_ * S_ + o] = acc;
        }
    }
    __syncwarp();

    // normalize wht in place -> wtn
    if (lane < K_) {
        float* r = s_wht[w] + lane * S_;
        float nq = 0.0f;
        #pragma unroll
        for (int s = 0; s < S_; s++) nq += r[s] * r[s];
        float inv = 1.0f / (sqrtf(nq) + 1e-8f);
        #pragma unroll
        for (int s = 0; s < S_; s++) r[s] *= inv;
    }
    __syncwarp();

    // pairs (k,l): dist + cluster loss — f32x2 FMA, fast log
    float cl = 0.0f, ds = 0.0f;
    #pragma unroll
    for (int it = 0; it < 13; it++) {
        int i = lane + it * 32;
        if (it < 12 || i < K_ * K_) {
            int k = i / K_, l = i % K_;
            const ulonglong2* wk = (const ulonglong2*)(s_wht[w] + k * S_);
            const ulonglong2* wl = (const ulonglong2*)(s_wht[w] + l * S_);
            unsigned long long d2 = pack2(0.0f, 0.0f);
            #pragma unroll
            for (int q = 0; q < 3; q++) {
                ulonglong2 a = wk[q], c4 = wl[q];
                ffma2(d2, a.x, c4.x);
                ffma2(d2, a.y, c4.y);
            }
            float d = sum2(d2);
            ds += d;
            if (k != l) {
                const ulonglong2* ak = (const ulonglong2*)(s_att[w] + k * SA);
                const ulonglong2* al = (const ulonglong2*)(s_att[w] + l * SA);
                unsigned long long p2 = pack2(0.0f, 0.0f);
                #pragma unroll
                for (int q = 0; q < 3; q++) {
                    ulonglong2 a = ak[q], c4 = al[q];
                    ffma2(p2, a.x, c4.x);
                    ffma2(p2, a.y, c4.y);
                }
                float p = sum2(p2);
                p = fminf(fmaxf(p, 1e-4f), 1.0f - 1e-4f);
                float lp = __logf(p);
                float same = (d >= 0.5f) ? 1.0f : 0.0f;
                cl += (1.0f - 2.0f * same) * lp;
            }
        }
    }
    #pragma unroll
    for (int off = 16; off > 0; off >>= 1) {
        cl += __shfl_down_sync(0xffffffffu, cl, off);
        ds += __shfl_down_sync(0xffffffffu, ds, off);
    }
    if (lane == 0) { g_clp[bn] = cl; g_dsp[bn] = ds; }
}

// ---------------------------------------------------------------------------
// Kernel 3: deterministic final reduction of scalars (1024 threads)
// ---------------------------------------------------------------------------
__global__ void __launch_bounds__(1024)
k_reduce(float* __restrict__ out, int scalar_base) {
    __shared__ double red[1024];
    int t = threadIdx.x;
    double cl = 0.0, ds = 0.0, wh = 0.0;
    for (int i = t; i < BN; i += 1024) { cl += (double)g_clp[i]; ds += (double)g_dsp[i]; }
    for (int i = t; i < K1_BLOCKS; i += 1024) wh += (double)g_whp[i];

    red[t] = cl; __syncthreads();
    for (int s = 512; s > 0; s >>= 1) { if (t < s) red[t] += red[t + s]; __syncthreads(); }
    double clsum = red[0]; __syncthreads();

    red[t] = ds; __syncthreads();
    for (int s = 512; s > 0; s >>= 1) { if (t < s) red[t] += red[t + s]; __syncthreads(); }
    double dsum = red[0]; __syncthreads();

    red[t] = wh; __syncthreads();
    for (int s = 512; s > 0; s >>= 1) { if (t < s) red[t] += red[t + s]; __syncthreads(); }
    double whsum = red[0];

    if (t == 0) {
        out[scalar_base + 0] = (float)(clsum / (double)BN);
        out[scalar_base + 1] = (float)(dsum / ((double)BN * K_ * K_));
        out[scalar_base + 2] = (float)(whsum / ((double)BN * S_));
    }
}

// ---------------------------------------------------------------------------
// Launch. Input order: fushed_features (unused), input_data, w_W, w_b,
// a1_W, a1_b, a2_W, a2_b, adj_mx_topk_index.
// ---------------------------------------------------------------------------
extern "C" void kernel_launch(void* const* d_in, const int* in_sizes, int n_in,
                              void* d_out, int out_size) {
    const float* input_data = (const float*)d_in[1];
    const float* wW  = (const float*)d_in[2];
    const float* wb  = (const float*)d_in[3];
    const float* a1W = (const float*)d_in[4];
    const float* a1b = (const float*)d_in[5];
    const float* a2W = (const float*)d_in[6];
    const float* a2b = (const float*)d_in[7];
    const int*   idx = (const int*)d_in[8];
    float* out = (float*)d_out;

    k_embed<<<K1_BLOCKS, 128>>>(input_data, wW, wb, a1W);
    k_main<<<BN / WPB, 256>>>(idx, a1b, a2W, a2b, out);
    k_reduce<<<1, 1024>>>(out, out_size - 3);
}